// round 3
// baseline (speedup 1.0000x reference)
#include <cuda_runtime.h>
#include <cuda_bf16.h>

// Problem constants
#define B_    64
#define N_    4096
#define E_    65536
#define T_    10
#define D_    128
#define PE_   32
#define L_    4
#define TN_   (T_ + N_)                 // 4106
#define EI_   (T_ * (T_ - 1))           // 90
#define ECH_  (T_ * N_)                 // 40960
#define ETOT_ (EI_ + E_ + 2 * ECH_)     // 147546

// Flat fp32 output segment sizes
#define S_X   (B_ * TN_ * D_)           // 33,636,352
#define S_PE  (B_ * TN_ * PE_)          //  8,409,088
#define S_EI  (2 * B_ * ETOT_)          // 18,885,888
#define S_EW  (B_ * ETOT_)              //  9,442,944
#define S_RT  (B_)                      // 64

// float4 segment offsets
#define O1_   (S_X / 4)
#define O2_   (O1_ + S_PE / 4)
#define O3_   (O2_ + S_EI / 4)
#define O4_   (O3_ + S_EW / 4)
#define TOT4_ (O4_ + S_RT / 4)          // 17,593,584

#define UNROLL_ 4
#define TPB_    256

__device__ __forceinline__ int ei_val(int r, int b, int k, const int* __restrict__ gei)
{
    int val;
    if (k < EI_) {
        int i0 = k / (T_ - 1);
        int m  = k - i0 * (T_ - 1);
        int jj = m + (m >= i0 ? 1 : 0);
        val = (r == 0) ? i0 : jj;
    } else if (k < EI_ + E_) {
        val = __ldcs(&gei[(b * 2 + r) * E_ + (k - EI_)]) + T_;
    } else {
        int c   = k - (EI_ + E_);
        bool rev = (c >= ECH_);
        int c2  = rev ? (c - ECH_) : c;
        int t   = c2 >> 12;
        int n   = c2 & (N_ - 1);
        int s, d;
        if (!rev) { s = t;      d = n + T_; }
        else      { s = n + T_; d = t;      }
        val = (r == 0) ? s : d;
    }
    return val + b * TN_;
}

__device__ __forceinline__ float ew_val(int b, int k,
                                        const int* __restrict__ spd,
                                        const float* __restrict__ param,
                                        const float* __restrict__ shw)
{
    if (k < EI_)        return __ldg(shw);
    if (k < EI_ + E_)   return 1.0f;
    int c  = k - (EI_ + E_);
    int c2 = (c >= ECH_) ? (c - ECH_) : c;
    int n  = c2 & (N_ - 1);
    int s  = __ldg(&spd[b * N_ + n]);
    s = min(max(s, 0), L_);
    return __ldg(&param[s]);
}

__device__ __forceinline__ float4 compute_val(
    int i,
    const float4* __restrict__ gx,  const float4* __restrict__ gpe,
    const int*    __restrict__ gei, const int*    __restrict__ spd,
    const int*    __restrict__ groot,
    const float4* __restrict__ tok, const float4* __restrict__ tpe,
    const float*  __restrict__ shw, const float*  __restrict__ param)
{
    float4 v;
    if (i < O1_) {
        // x segment: rows of 32 float4 (D=128)
        int row = i >> 5;
        int c   = i & 31;
        int b   = row / TN_;
        int r   = row - b * TN_;
        if (r < T_) v = __ldg(&tok[r * 32 + c]);
        else        v = __ldcs(&gx[((long long)b * N_ + (r - T_)) * 32 + c]);
    } else if (i < O2_) {
        // pe segment: rows of 8 float4 (PE=32)
        int p   = i - O1_;
        int row = p >> 3;
        int c   = p & 7;
        int b   = row / TN_;
        int r   = row - b * TN_;
        if (r < T_) v = __ldg(&tpe[r * 8 + c]);
        else        v = __ldcs(&gpe[((long long)b * N_ + (r - T_)) * 8 + c]);
    } else if (i < O3_) {
        // edge_index segment (4 scalar values per float4)
        int q  = (i - O2_) << 2;
        int r  = q / (B_ * ETOT_);
        int j0 = q - r * (B_ * ETOT_);
        #pragma unroll
        for (int u = 0; u < 4; u++) {
            int j = j0 + u;
            int b = j / ETOT_;
            int k = j - b * ETOT_;
            ((float*)&v)[u] = (float)ei_val(r, b, k, gei);
        }
    } else if (i < O4_) {
        // edge_weight segment
        int s0 = (i - O3_) << 2;
        #pragma unroll
        for (int u = 0; u < 4; u++) {
            int j = s0 + u;
            int b = j / ETOT_;
            int k = j - b * ETOT_;
            ((float*)&v)[u] = ew_val(b, k, spd, param, shw);
        }
    } else {
        // root segment
        int r0 = (i - O4_) << 2;
        #pragma unroll
        for (int u = 0; u < 4; u++) {
            int b = r0 + u;
            ((float*)&v)[u] = (float)(__ldg(&groot[b]) + T_ + b * TN_);
        }
    }
    return v;
}

__global__ void __launch_bounds__(TPB_) fused_all(
    const float4* __restrict__ gx,
    const float4* __restrict__ gpe,
    const int*    __restrict__ gei,
    const int*    __restrict__ spd,
    const int*    __restrict__ groot,
    const float4* __restrict__ tok,
    const float4* __restrict__ tpe,
    const float*  __restrict__ shw,
    const float*  __restrict__ param,
    float4*       __restrict__ out)
{
    // Block-contiguous tile of UNROLL_*TPB_ float4s; thread t covers
    // base + u*TPB_ + t  (perfect per-instruction coalescing, 4 independent
    // loads in flight before the first store).
    int base = blockIdx.x * (TPB_ * UNROLL_) + threadIdx.x;

    float4 v[UNROLL_];
    #pragma unroll
    for (int u = 0; u < UNROLL_; u++) {
        int i = base + u * TPB_;
        if (i < TOT4_)
            v[u] = compute_val(i, gx, gpe, gei, spd, groot, tok, tpe, shw, param);
    }
    #pragma unroll
    for (int u = 0; u < UNROLL_; u++) {
        int i = base + u * TPB_;
        if (i < TOT4_)
            __stcs(&out[i], v[u]);
    }
}

extern "C" void kernel_launch(void* const* d_in, const int* in_sizes, int n_in,
                              void* d_out, int out_size)
{
    const float4* g_x    = (const float4*)d_in[0];
    const float4* g_pe   = (const float4*)d_in[1];
    const int*    g_ei   = (const int*)   d_in[2];
    const int*    g_spd  = (const int*)   d_in[3];
    const int*    g_root = (const int*)   d_in[4];
    const float4* tok    = (const float4*)d_in[5];
    const float4* tok_pe = (const float4*)d_in[6];
    const float*  shw    = (const float*) d_in[7];
    const float*  ewp    = (const float*) d_in[8];

    int blocks = (TOT4_ + TPB_ * UNROLL_ - 1) / (TPB_ * UNROLL_);  // 17182
    fused_all<<<blocks, TPB_>>>(g_x, g_pe, g_ei, g_spd, g_root,
                                tok, tok_pe, shw, ewp, (float4*)d_out);
}

// round 4
// speedup vs baseline: 1.1282x; 1.1282x over previous
#include <cuda_runtime.h>
#include <cuda_bf16.h>

// Problem constants
#define B_    64
#define N_    4096
#define E_    65536
#define T_    10
#define D_    128
#define PE_   32
#define L_    4
#define TN_   (T_ + N_)                 // 4106
#define EI_   (T_ * (T_ - 1))           // 90
#define ECH_  (T_ * N_)                 // 40960
#define ETOT_ (EI_ + E_ + 2 * ECH_)     // 147546

// Flat fp32 output segment sizes
#define S_X   (B_ * TN_ * D_)           // 33,636,352
#define S_PE  (B_ * TN_ * PE_)          //  8,409,088
#define S_EI  (2 * B_ * ETOT_)          // 18,885,888
#define S_EW  (B_ * ETOT_)              //  9,442,944
#define S_RT  (B_)                      // 64

// float4 counts per segment
#define F4_X   (S_X  / 4)               //  8,409,088
#define F4_PE  (S_PE / 4)               //  2,102,272
#define F4_EI  (S_EI / 4)               //  4,721,472
#define F4_EWR ((S_EW + S_RT) / 4)      //  2,360,752 (edge_weight + root)

// float4 output offsets
#define O1_   F4_X
#define O2_   (O1_ + F4_PE)
#define O3_   (O2_ + F4_EI)

#define TPB_   256
#define UPB_   (TPB_ * 2)               // 512 float4 per block (unroll 2)

// Block ranges (compile-time)
#define NB_X   (F4_X  / UPB_)           // 16424  (exact)
#define NB_PE  (F4_PE / UPB_)           // 4106   (exact)
#define NB_EI  ((F4_EI  + UPB_ - 1) / UPB_)   // 9222
#define NB_EWR ((F4_EWR + UPB_ - 1) / UPB_)   // 4611
#define NB_TOT (NB_X + NB_PE + NB_EI + NB_EWR)

// edge_index value for (row r, batch b, local edge k) — identical to reference
__device__ __forceinline__ int ei_val(int r, int b, int k, const int* __restrict__ gei)
{
    int val;
    if (k < EI_) {
        int i0 = k / (T_ - 1);
        int m  = k - i0 * (T_ - 1);
        int jj = m + (m >= i0 ? 1 : 0);
        val = (r == 0) ? i0 : jj;
    } else if (k < EI_ + E_) {
        val = __ldcs(&gei[(b * 2 + r) * E_ + (k - EI_)]) + T_;
    } else {
        int c   = k - (EI_ + E_);
        bool rev = (c >= ECH_);
        int c2  = rev ? (c - ECH_) : c;
        int t   = c2 >> 12;
        int n   = c2 & (N_ - 1);
        int s, d;
        if (!rev) { s = t;      d = n + T_; }
        else      { s = n + T_; d = t;      }
        val = (r == 0) ? s : d;
    }
    return val + b * TN_;
}

__device__ __forceinline__ float ew_val(int b, int k,
                                        const int* __restrict__ spd,
                                        const float* __restrict__ param,
                                        const float* __restrict__ shw)
{
    if (k < EI_)        return __ldg(shw);
    if (k < EI_ + E_)   return 1.0f;
    int c  = k - (EI_ + E_);
    int c2 = (c >= ECH_) ? (c - ECH_) : c;
    int n  = c2 & (N_ - 1);
    int s  = __ldg(&spd[b * N_ + n]);
    s = min(max(s, 0), L_);
    return __ldg(&param[s]);
}

__global__ void __launch_bounds__(TPB_) fused_all(
    const float4* __restrict__ gx,
    const float4* __restrict__ gpe,
    const int*    __restrict__ gei,
    const int*    __restrict__ spd,
    const int*    __restrict__ groot,
    const float4* __restrict__ tok,
    const float4* __restrict__ tpe,
    const float*  __restrict__ shw,
    const float*  __restrict__ param,
    float4*       __restrict__ out)
{
    const int t   = threadIdx.x;
    const int blk = blockIdx.x;

    if (blk < NB_X) {
        // ---------------- x segment (block-uniform, no bounds checks)
        int i0 = blk * UPB_ + t;            // and i0 + TPB_
        float4 v0, v1;
        {
            int i = i0;
            int row = i >> 5, c = i & 31;
            int b = row / TN_, r = row - b * TN_;
            v0 = (r < T_) ? __ldg(&tok[r * 32 + c])
                          : __ldcs(&gx[((long long)b * N_ + (r - T_)) * 32 + c]);
        }
        {
            int i = i0 + TPB_;
            int row = i >> 5, c = i & 31;
            int b = row / TN_, r = row - b * TN_;
            v1 = (r < T_) ? __ldg(&tok[r * 32 + c])
                          : __ldcs(&gx[((long long)b * N_ + (r - T_)) * 32 + c]);
        }
        __stcs(&out[i0], v0);
        __stcs(&out[i0 + TPB_], v1);
    } else if (blk < NB_X + NB_PE) {
        // ---------------- pe segment
        int p0 = (blk - NB_X) * UPB_ + t;
        float4 v0, v1;
        {
            int p = p0;
            int row = p >> 3, c = p & 7;
            int b = row / TN_, r = row - b * TN_;
            v0 = (r < T_) ? __ldg(&tpe[r * 8 + c])
                          : __ldcs(&gpe[((long long)b * N_ + (r - T_)) * 8 + c]);
        }
        {
            int p = p0 + TPB_;
            int row = p >> 3, c = p & 7;
            int b = row / TN_, r = row - b * TN_;
            v1 = (r < T_) ? __ldg(&tpe[r * 8 + c])
                          : __ldcs(&gpe[((long long)b * N_ + (r - T_)) * 8 + c]);
        }
        __stcs(&out[O1_ + p0], v0);
        __stcs(&out[O1_ + p0 + TPB_], v1);
    } else if (blk < NB_X + NB_PE + NB_EI) {
        // ---------------- edge_index segment
        int q0 = (blk - NB_X - NB_PE) * UPB_ + t;
        #pragma unroll
        for (int u = 0; u < 2; u++) {
            int q = q0 + u * TPB_;
            if (q >= F4_EI) break;
            int j = q << 2;                         // scalar index in [0, 2*B*ETOT)
            int r = (q >= (F4_EI / 2)) ? 1 : 0;     // row (half-way split, exact)
            j -= r * (B_ * ETOT_);
            int b = j / ETOT_;                      // one divide per float4
            int k = j - b * ETOT_;
            float4 v;
            #pragma unroll
            for (int w = 0; w < 4; w++) {
                ((float*)&v)[w] = (float)ei_val(r, b, k, gei);
                if (++k == ETOT_) { k = 0; b++; }
            }
            __stcs(&out[O2_ + q], v);
        }
    } else {
        // ---------------- edge_weight (+root) segment
        int s0 = (blk - NB_X - NB_PE - NB_EI) * UPB_ + t;
        #pragma unroll
        for (int u = 0; u < 2; u++) {
            int s = s0 + u * TPB_;
            if (s >= F4_EWR) break;
            float4 v;
            if (s < F4_EWR - (S_RT / 4)) {
                int j = s << 2;
                int b = j / ETOT_;
                int k = j - b * ETOT_;
                #pragma unroll
                for (int w = 0; w < 4; w++) {
                    ((float*)&v)[w] = ew_val(b, k, spd, param, shw);
                    if (++k == ETOT_) { k = 0; b++; }
                }
            } else {
                int r0 = (s - (F4_EWR - S_RT / 4)) << 2;
                #pragma unroll
                for (int w = 0; w < 4; w++) {
                    int b = r0 + w;
                    ((float*)&v)[w] = (float)(__ldg(&groot[b]) + T_ + b * TN_);
                }
            }
            __stcs(&out[O3_ + s], v);
        }
    }
}

extern "C" void kernel_launch(void* const* d_in, const int* in_sizes, int n_in,
                              void* d_out, int out_size)
{
    const float4* g_x    = (const float4*)d_in[0];
    const float4* g_pe   = (const float4*)d_in[1];
    const int*    g_ei   = (const int*)   d_in[2];
    const int*    g_spd  = (const int*)   d_in[3];
    const int*    g_root = (const int*)   d_in[4];
    const float4* tok    = (const float4*)d_in[5];
    const float4* tok_pe = (const float4*)d_in[6];
    const float*  shw    = (const float*) d_in[7];
    const float*  ewp    = (const float*) d_in[8];

    fused_all<<<NB_TOT, TPB_>>>(g_x, g_pe, g_ei, g_spd, g_root,
                                tok, tok_pe, shw, ewp, (float4*)d_out);
}